// round 7
// baseline (speedup 1.0000x reference)
#include <cuda_runtime.h>
#include <cuda_bf16.h>
#include <math.h>
#include <stdint.h>

#define CB_K   1024
#define CH     128
#define QELEMS 8388608
#define NBLK   2048

__device__ float g_c2[CB_K];
__device__ int   g_maxc2bits = 0;
__device__ float g_partial[NBLK];
__device__ unsigned short g_cbbf[CB_K * 136];   // bf16 codebook, row stride 136 u16

// ---------------- helpers ----------------
__device__ __forceinline__ uint32_t smem_u32(const void* p) {
    uint32_t a;
    asm("{ .reg .u64 t; cvta.to.shared.u64 t, %1; cvt.u32.u64 %0, t; }" : "=r"(a) : "l"(p));
    return a;
}
__device__ __forceinline__ void cp_async16(uint32_t d, const void* s) {
    asm volatile("cp.async.cg.shared.global [%0], [%1], 16;" :: "r"(d), "l"(s));
}
#define CP_COMMIT() asm volatile("cp.async.commit_group;")
__device__ __forceinline__ uint32_t packbf(float lo, float hi) {
    uint32_t d;
    asm("cvt.rn.bf16x2.f32 %0, %1, %2;" : "=r"(d) : "f"(hi), "f"(lo));
    return d;
}
#define LDSM4(rr, addr)                                                          \
    asm volatile("ldmatrix.sync.aligned.m8n8.x4.shared.b16 {%0,%1,%2,%3}, [%4];" \
        : "=r"((rr)[0]),"=r"((rr)[1]),"=r"((rr)[2]),"=r"((rr)[3]) : "r"(addr))
#define LDSM2(r0, r1, addr)                                                      \
    asm volatile("ldmatrix.sync.aligned.m8n8.x2.shared.b16 {%0,%1}, [%2];"       \
        : "=r"(r0),"=r"(r1) : "r"(addr))
#define MMA(dd, aa, b0, b1)                                                      \
    asm volatile("mma.sync.aligned.m16n8k16.row.col.f32.bf16.bf16.f32 "          \
        "{%0,%1,%2,%3}, {%4,%5,%6,%7}, {%8,%9}, {%0,%1,%2,%3};"                  \
        : "+f"((dd)[0]),"+f"((dd)[1]),"+f"((dd)[2]),"+f"((dd)[3])                \
        : "r"((aa)[0]),"r"((aa)[1]),"r"((aa)[2]),"r"((aa)[3]), "r"(b0),"r"(b1))

// ---------------------------------------------------------------------------
__global__ void prep_kernel(const float* __restrict__ codebook) {
    int k = blockIdx.x, c = threadIdx.x;
    float v = codebook[k * CH + c];
    __nv_bfloat16 hh = __float2bfloat16(v);
    g_cbbf[k * 136 + c] = *reinterpret_cast<unsigned short*>(&hh);
    float s = v * v;
    #pragma unroll
    for (int o = 16; o > 0; o >>= 1) s += __shfl_down_sync(0xffffffffu, s, o);
    __shared__ float ws[4];
    if ((c & 31) == 0) ws[c >> 5] = s;
    __syncthreads();
    if (c == 0) {
        float c2 = (ws[0] + ws[1]) + (ws[2] + ws[3]);
        g_c2[k] = c2;
        atomicMax(&g_maxc2bits, __float_as_int(c2));
    }
}

// ---------------------------------------------------------------------------
// Fused kernel, M=32 vectors/CTA, 2 CTAs/SM. SMEM word offsets:
// ---------------------------------------------------------------------------
#define W_E    0        // e32[32][513] offset-bf16 pairs; A image overlays start
#define W_ZST  16416    // raw x fp32 [c][v] 128x32
#define W_CB0  20512    // B tile 0: 32 codes x 136 u16 (2176 words)
#define W_CB1  22688
#define W_C2   24864
#define W_NP   25888    // norm partials 8x32
#define W_RN2  26144
#define W_Z2   26176
#define W_RINV 26208
#define W_PM   26240    // 8x32
#define W_PE   26496
#define W_PIX  26752
#define W_LS   27008
#define W_SIDX 27040
#define SMEM_WORDS 27072
#define SMEM_BYTES (SMEM_WORDS * 4)

__device__ __forceinline__ void issue_tile(uint32_t dstb, int j, int tid) {
    const unsigned char* src = reinterpret_cast<const unsigned char*>(g_cbbf)
                               + (size_t)j * 8704;
    #pragma unroll
    for (int it = 0; it < 3; ++it) {
        int idx = it * 256 + tid;
        if (idx < 544) cp_async16(dstb + idx * 16, src + idx * 16);
    }
    CP_COMMIT();
}

__global__ void __launch_bounds__(256, 2)
vq_fused(const float* __restrict__ x, const float* __restrict__ codebook,
         float* __restrict__ out) {
    extern __shared__ uint32_t su[];
    float* sf = reinterpret_cast<float*>(su);
    int*   si = reinterpret_cast<int*>(su);
    const uint32_t sb = smem_u32(su);
    const int tid = threadIdx.x, w = tid >> 5, lane = tid & 31;
    const int rg = w >> 2, ch2 = w & 3;      // row-group(16) / 8-code col group
    const int n0 = blockIdx.x * 32;
    const int b = n0 >> 12, h = (n0 >> 6) & 63, w0 = n0 & 63;

    issue_tile(sb + W_CB0 * 4, 0, tid);
    issue_tile(sb + W_CB1 * 4, 1, tid);

    // raw x tile -> zsT[c][v] (128B coalesced per warp)
    const float* xbase = x + (size_t)b * (CH * 4096) + h * 64 + w0;
    #pragma unroll
    for (int it = 0; it < 16; ++it) {
        int idx = it * 256 + tid;
        sf[W_ZST + idx] = xbase[(idx >> 5) * 4096 + (idx & 31)];
    }
    #pragma unroll
    for (int i = 0; i < 4; ++i) sf[W_C2 + i * 256 + tid] = g_c2[i * 256 + tid];
    __syncthreads();

    // norms: 8 threads per vector, 16 channels each
    {
        int v = tid & 31, seg = tid >> 5;
        float s0 = 0.f, s1 = 0.f;
        #pragma unroll
        for (int i = 0; i < 8; ++i) {
            int c = seg * 16 + 2 * i;
            float a0 = sf[W_ZST + c * 32 + v], a1 = sf[W_ZST + (c + 1) * 32 + v];
            s0 = fmaf(a0, a0, s0); s1 = fmaf(a1, a1, s1);
        }
        sf[W_NP + seg * 32 + v] = s0 + s1;
    }
    __syncthreads();
    if (tid < 32) {
        float s = 0.f;
        #pragma unroll
        for (int sg = 0; sg < 8; ++sg) s += sf[W_NP + sg * 32 + tid];
        float r = 1.0f / fmaxf(sqrtf(s), 1e-12f);
        sf[W_RINV + tid] = r;
        sf[W_RN2  + tid] = 2.0f * r;
        sf[W_Z2   + tid] = s * r * r;
    }
    __syncthreads();

    // bf16 A image (normalized z): 32 rows x 136-u16 stride, overlays W_E
    {
        int m = tid >> 3, qq = tid & 7;
        float r = sf[W_RINV + m];
        uint32_t* dst = su + m * 68 + qq * 8;
        #pragma unroll
        for (int i = 0; i < 8; ++i) {
            int c = qq * 16 + 2 * i;
            dst[i] = packbf(sf[W_ZST + c * 32 + m] * r,
                            sf[W_ZST + (c + 1) * 32 + m] * r);
        }
    }
    __syncthreads();

    // A fragments: rows 16*rg..+15, all K
    uint32_t a[8][4];
    #pragma unroll
    for (int kk = 0; kk < 8; ++kk) {
        uint32_t ad = sb + (16 * rg + (lane & 15)) * 272 + (kk * 16 + (lane >> 4) * 8) * 2;
        LDSM4(a[kk], ad);
    }
    __syncthreads();   // A image region now reusable as e storage

    const float OFF = 0.75f * __int_as_float(g_maxc2bits);

    for (int j = 0; j < 32; ++j) {
        asm volatile("cp.async.wait_group 1;" ::: "memory");
        if (j == 31) asm volatile("cp.async.wait_group 0;" ::: "memory");
        __syncthreads();
        const uint32_t cb = sb + ((j & 1) ? W_CB1 : W_CB0) * 4;

        float d[4] = {0.f, 0.f, 0.f, 0.f};
        #pragma unroll
        for (int kk = 0; kk < 8; ++kk) {
            uint32_t b0, b1;
            uint32_t ba = cb + ((ch2 * 8 + (lane & 7)) * 136
                        + kk * 16 + ((lane >> 3) & 1) * 8) * 2;
            LDSM2(b0, b1, ba);
            MMA(d, a[kk], b0, b1);
        }

        // epilogue: eoff = c2 - 2*dot - OFF, packed bf16 pairs into e32
        int r0 = 16 * rg + (lane >> 2);
        int k0 = j * 32 + ch2 * 8 + 2 * (lane & 3);
        float cv0 = sf[W_C2 + k0]     - OFF;
        float cv1 = sf[W_C2 + k0 + 1] - OFF;
        su[W_E + r0 * 513 + (k0 >> 1)] =
            packbf(fmaf(-2.f, d[0], cv0), fmaf(-2.f, d[1], cv1));
        su[W_E + (r0 + 8) * 513 + (k0 >> 1)] =
            packbf(fmaf(-2.f, d[2], cv0), fmaf(-2.f, d[3], cv1));
        __syncthreads();
        if (j + 2 < 32) issue_tile(sb + ((j & 1) ? W_CB1 : W_CB0) * 4, j + 2, tid);
    }

    // ---- filter min over offset-bf16 e (8 threads/vector, 64 words each) ----
    const int v = tid & 31, q = tid >> 5;
    {
        float mn = 3.4e38f;
        const uint32_t* dr = su + W_E + v * 513 + q * 64;
        #pragma unroll 4
        for (int ww = 0; ww < 64; ++ww) {
            uint32_t u = dr[ww];
            float f0 = __uint_as_float(u << 16);
            float f1 = __uint_as_float(u & 0xFFFF0000u);
            mn = fminf(mn, fminf(f0, f1));
        }
        sf[W_PM + q * 32 + v] = mn;
    }
    __syncthreads();
    if (tid < 32) {
        float m = sf[W_PM + tid];
        #pragma unroll
        for (int qq = 1; qq < 8; ++qq) m = fminf(m, sf[W_PM + qq * 32 + tid]);
        sf[W_PM + tid] = m;
    }
    __syncthreads();

    // ---- exact fp32 rescore of window candidates ----
    {
        float wnd = sqrtf(__int_as_float(g_maxc2bits)) * 0.06f;
        float T = sf[W_PM + v] + wnd;
        float r2 = sf[W_RN2 + v];
        float be = 3.4e38f; int bi = 0x7fffffff;
        const uint32_t* dr = su + W_E + v * 513 + q * 64;
        for (int ww = 0; ww < 64; ++ww) {
            uint32_t u = dr[ww];
            #pragma unroll
            for (int hb = 0; hb < 2; ++hb) {
                float f = hb ? __uint_as_float(u & 0xFFFF0000u)
                             : __uint_as_float(u << 16);
                if (f <= T) {
                    int k = q * 128 + 2 * ww + hb;
                    const float* cr = codebook + k * CH;
                    float d0 = 0.f, d1 = 0.f, d2 = 0.f, d3 = 0.f;
                    #pragma unroll
                    for (int c = 0; c < 128; c += 4) {
                        d0 = fmaf(sf[W_ZST + (c+0)*32 + v], cr[c+0], d0);
                        d1 = fmaf(sf[W_ZST + (c+1)*32 + v], cr[c+1], d1);
                        d2 = fmaf(sf[W_ZST + (c+2)*32 + v], cr[c+2], d2);
                        d3 = fmaf(sf[W_ZST + (c+3)*32 + v], cr[c+3], d3);
                    }
                    float ef = fmaf(-r2, (d0 + d1) + (d2 + d3), sf[W_C2 + k]);
                    if (ef < be) { be = ef; bi = k; }   // ascending k: ties -> smaller
                }
            }
        }
        sf[W_PE + q * 32 + v] = be;
        si[W_PIX + q * 32 + v] = bi;
    }
    __syncthreads();
    if (tid < 32) {
        float be = sf[W_PE + tid]; int bi = si[W_PIX + tid];
        #pragma unroll
        for (int qq = 1; qq < 8; ++qq) {
            float e2 = sf[W_PE + qq * 32 + tid];
            int   i2 = si[W_PIX + qq * 32 + tid];
            if (e2 < be || (e2 == be && i2 < bi)) { be = e2; bi = i2; }
        }
        si[W_SIDX + tid] = bi;
        sf[W_LS + tid] = sqrtf(fmaxf(sf[W_Z2 + tid] + be, 0.f));
    }
    __syncthreads();
    if (tid == 0) {
        float s = 0.f;
        #pragma unroll
        for (int i = 0; i < 32; ++i) s += sf[W_LS + i];
        g_partial[blockIdx.x] = s;
    }
    __syncthreads();

    // ---- q gather (coalesced codebook reads) + coalesced store ----
    float* qr = sf + W_E;   // [32][129]
    {
        int wrp = tid >> 5, ln = tid & 31;
        #pragma unroll
        for (int vv = 0; vv < 4; ++vv) {
            int vx = wrp * 4 + vv;
            const float* cr = codebook + si[W_SIDX + vx] * CH;
            #pragma unroll
            for (int cc = 0; cc < 4; ++cc) {
                int c = cc * 32 + ln;
                qr[vx * 129 + c] = cr[c];
            }
        }
    }
    __syncthreads();
    {
        float* obase = out + (size_t)b * (CH * 4096) + h * 64 + w0;
        const int ww = tid & 31, c0 = tid >> 5;
        #pragma unroll
        for (int it = 0; it < 16; ++it) {
            int c = it * 8 + c0;
            obase[c * 4096 + ww] = qr[ww * 129 + c];
        }
    }
}

// ---------------------------------------------------------------------------
__global__ void finalize_kernel(float* __restrict__ out) {
    __shared__ float s[256];
    int t = threadIdx.x;
    float a = 0.f;
    #pragma unroll
    for (int i = 0; i < 8; ++i) a += g_partial[t + i * 256];
    s[t] = a;
    __syncthreads();
    for (int off = 128; off > 0; off >>= 1) {
        if (t < off) s[t] += s[t + off];
        __syncthreads();
    }
    if (t == 0) {
        float mean = s[0] * (1.0f / 65536.0f);
        out[QELEMS]     = 0.25f * mean;
        out[QELEMS + 1] = mean;
    }
}

extern "C" void kernel_launch(void* const* d_in, const int* in_sizes, int n_in,
                              void* d_out, int out_size) {
    const float* x        = (const float*)d_in[0];
    const float* codebook = (const float*)d_in[1];
    float*       out      = (float*)d_out;

    prep_kernel<<<CB_K, CH>>>(codebook);

    cudaFuncSetAttribute(vq_fused, cudaFuncAttributeMaxDynamicSharedMemorySize, SMEM_BYTES);
    vq_fused<<<NBLK, 256, SMEM_BYTES>>>(x, codebook, out);

    if (out_size >= QELEMS + 2)
        finalize_kernel<<<1, 256>>>(out);
}

// round 8
// speedup vs baseline: 1.3363x; 1.3363x over previous
#include <cuda_runtime.h>
#include <cuda_bf16.h>
#include <math.h>
#include <stdint.h>

#define CB_K   1024
#define CH     128
#define QELEMS 8388608
#define NBLK   1024

__device__ float g_c2[CB_K];
__device__ int   g_maxc2bits = 0;
__device__ float g_partial[NBLK];
__device__ unsigned short g_cbbf[CB_K * 136];   // bf16 codebook, row stride 136 u16

// ---------------- helpers ----------------
__device__ __forceinline__ uint32_t smem_u32(const void* p) {
    uint32_t a;
    asm("{ .reg .u64 t; cvta.to.shared.u64 t, %1; cvt.u32.u64 %0, t; }" : "=r"(a) : "l"(p));
    return a;
}
__device__ __forceinline__ void cp_async16(uint32_t d, const void* s) {
    asm volatile("cp.async.cg.shared.global [%0], [%1], 16;" :: "r"(d), "l"(s));
}
#define CP_COMMIT() asm volatile("cp.async.commit_group;")
__device__ __forceinline__ uint32_t packbf(float lo, float hi) {
    uint32_t d;
    asm("cvt.rn.bf16x2.f32 %0, %1, %2;" : "=r"(d) : "f"(hi), "f"(lo));
    return d;
}
#define LDSM4(rr, addr)                                                          \
    asm volatile("ldmatrix.sync.aligned.m8n8.x4.shared.b16 {%0,%1,%2,%3}, [%4];" \
        : "=r"((rr)[0]),"=r"((rr)[1]),"=r"((rr)[2]),"=r"((rr)[3]) : "r"(addr))
#define MMA(dd, aa, b0, b1)                                                      \
    asm volatile("mma.sync.aligned.m16n8k16.row.col.f32.bf16.bf16.f32 "          \
        "{%0,%1,%2,%3}, {%4,%5,%6,%7}, {%8,%9}, {%0,%1,%2,%3};"                  \
        : "+f"((dd)[0]),"+f"((dd)[1]),"+f"((dd)[2]),"+f"((dd)[3])                \
        : "r"((aa)[0]),"r"((aa)[1]),"r"((aa)[2]),"r"((aa)[3]), "r"(b0),"r"(b1))

// ---------------------------------------------------------------------------
__global__ void prep_kernel(const float* __restrict__ codebook) {
    int k = blockIdx.x, c = threadIdx.x;
    float v = codebook[k * CH + c];
    __nv_bfloat16 hh = __float2bfloat16(v);
    g_cbbf[k * 136 + c] = *reinterpret_cast<unsigned short*>(&hh);
    float s = v * v;
    #pragma unroll
    for (int o = 16; o > 0; o >>= 1) s += __shfl_down_sync(0xffffffffu, s, o);
    __shared__ float ws[4];
    if ((c & 31) == 0) ws[c >> 5] = s;
    __syncthreads();
    if (c == 0) {
        float c2 = (ws[0] + ws[1]) + (ws[2] + ws[3]);
        g_c2[k] = c2;
        atomicMax(&g_maxc2bits, __float_as_int(c2));
    }
}

// ---------------------------------------------------------------------------
// SMEM word offsets (total 24192 words = 96.8KB -> 2 CTAs/SM)
//   W_ZST 0      : raw x fp32 [c][v] 128x64
//   W_CB  8192   : 3 B-buffers x 4352 words (buf2 doubles as bf16 A image)
//   W_C2  21248, W_NP 22272 (8x64), W_RN2 22784, W_Z2 22848, W_RINV 22912,
//   W_T 22976, W_PE 23040, W_PIX 23552, W_LS 24064, W_SIDX 24128
// qr[64][129] overlays W_CB after the MMA loops.
// ---------------------------------------------------------------------------
#define W_ZST  0
#define W_CB   8192
#define W_AIMG 16896
#define W_C2   21248
#define W_NP   22272
#define W_RN2  22784
#define W_Z2   22848
#define W_RINV 22912
#define W_T    22976
#define W_PE   23040
#define W_PIX  23552
#define W_LS   24064
#define W_SIDX 24128
#define SMEM_WORDS 24192
#define SMEM_BYTES (SMEM_WORDS * 4)

__device__ __forceinline__ void issue_tile(uint32_t dstb, int j, int tid) {
    const unsigned char* src = reinterpret_cast<const unsigned char*>(g_cbbf)
                               + (size_t)j * 17408;
    #pragma unroll
    for (int it = 0; it < 5; ++it) {
        int idx = it * 256 + tid;
        if (idx < 1088) cp_async16(dstb + idx * 16, src + idx * 16);
    }
    CP_COMMIT();
}

__global__ void __launch_bounds__(256, 2)
vq_fused(const float* __restrict__ x, const float* __restrict__ codebook,
         float* __restrict__ out) {
    extern __shared__ uint32_t su[];
    float* sf = reinterpret_cast<float*>(su);
    int*   si = reinterpret_cast<int*>(su);
    const uint32_t sb = smem_u32(su);
    const int tid = threadIdx.x, w = tid >> 5, lane = tid & 31;
    const int wp = w >> 1, chh = w & 1;
    const int n0 = blockIdx.x * 64;
    const int b = n0 >> 12, h = (n0 >> 6) & 63;

    issue_tile(sb + (W_CB + 0 * 4352) * 4, 0, tid);
    issue_tile(sb + (W_CB + 1 * 4352) * 4, 1, tid);

    // raw x tile -> zsT[c][v]
    const float* xbase = x + (size_t)b * (CH * 4096) + h * 64;
    {
        const int ww = tid & 63, c0 = tid >> 6;
        #pragma unroll
        for (int it = 0; it < 32; ++it) {
            int c = it * 4 + c0;
            sf[W_ZST + c * 64 + ww] = xbase[c * 4096 + ww];
        }
    }
    #pragma unroll
    for (int i = 0; i < 4; ++i) sf[W_C2 + i * 256 + tid] = g_c2[i * 256 + tid];
    __syncthreads();

    // norms: 4 threads per vector
    {
        int v = tid & 63, seg = tid >> 6;
        float s0 = 0.f, s1 = 0.f;
        #pragma unroll
        for (int i = 0; i < 16; ++i) {
            int c = seg * 32 + 2 * i;
            float a0 = sf[W_ZST + c * 64 + v], a1 = sf[W_ZST + (c + 1) * 64 + v];
            s0 = fmaf(a0, a0, s0); s1 = fmaf(a1, a1, s1);
        }
        sf[W_NP + seg * 64 + v] = s0 + s1;
    }
    __syncthreads();
    if (tid < 64) {
        float s = (sf[W_NP + tid] + sf[W_NP + 64 + tid])
                + (sf[W_NP + 128 + tid] + sf[W_NP + 192 + tid]);
        float r = 1.0f / fmaxf(sqrtf(s), 1e-12f);
        sf[W_RINV + tid] = r;
        sf[W_RN2  + tid] = 2.0f * r;
        sf[W_Z2   + tid] = s * r * r;
    }
    __syncthreads();

    // bf16 A image (normalized z) into buf2 region: 64 rows x 272B
    {
        int m = tid >> 2, qq = tid & 3;
        float r = sf[W_RINV + m];
        uint32_t* dst = su + W_AIMG + m * 68 + qq * 16;
        #pragma unroll
        for (int i = 0; i < 16; ++i) {
            int c = qq * 32 + 2 * i;
            dst[i] = packbf(sf[W_ZST + c * 64 + m] * r,
                            sf[W_ZST + (c + 1) * 64 + m] * r);
        }
    }
    __syncthreads();

    // A fragments: rows 16*wp..+15, all K
    uint32_t a[8][4];
    #pragma unroll
    for (int kk = 0; kk < 8; ++kk) {
        uint32_t ad = sb + W_AIMG * 4 + (16 * wp + (lane & 15)) * 272
                    + (kk * 16 + (lane >> 4) * 8) * 2;
        LDSM4(a[kk], ad);
    }
    __syncthreads();   // buf2 now free for B tiles

    const float OFF = 0.75f * __int_as_float(g_maxc2bits);
    const float wnd = sqrtf(__int_as_float(g_maxc2bits)) * 0.06f;
    const int r0 = 16 * wp + (lane >> 2);
    const int slot = chh * 4 + (lane & 3);

    float mn[2] = {3.4e38f, 3.4e38f};
    float be[2] = {3.4e38f, 3.4e38f};
    int   bi[2] = {0x7fffffff, 0x7fffffff};

    for (int jj = 0; jj < 32; ++jj) {
        if (jj < 31) asm volatile("cp.async.wait_group 1;" ::: "memory");
        else         asm volatile("cp.async.wait_group 0;" ::: "memory");
        __syncthreads();   // copies visible + prior tile's readers done
        if (jj + 2 < 32)
            issue_tile(sb + (W_CB + ((jj + 2) % 3) * 4352) * 4, (jj + 2) & 15, tid);

        if (jj == 16) {   // pass-1 -> threshold reduce
            sf[W_NP + slot * 64 + r0]     = mn[0];
            sf[W_NP + slot * 64 + r0 + 8] = mn[1];
            __syncthreads();
            if (tid < 64) {
                float m = sf[W_NP + tid];
                #pragma unroll
                for (int qq = 1; qq < 8; ++qq) m = fminf(m, sf[W_NP + qq * 64 + tid]);
                sf[W_T + tid] = m + wnd;
            }
            __syncthreads();
        }

        const uint32_t cbb = sb + (W_CB + (jj % 3) * 4352) * 4;
        const int j = jj & 15;

        float d[4][4];
        #pragma unroll
        for (int f = 0; f < 4; ++f)
            #pragma unroll
            for (int i = 0; i < 4; ++i) d[f][i] = 0.f;

        #pragma unroll
        for (int kk = 0; kk < 8; ++kk) {
            #pragma unroll
            for (int gg = 0; gg < 2; ++gg) {
                uint32_t bfr[4];
                uint32_t ba = cbb + ((chh * 32 + gg * 16 + (lane & 7) + ((lane >> 4) & 1) * 8) * 136
                            + kk * 16 + ((lane >> 3) & 1) * 8) * 2;
                LDSM4(bfr, ba);
                MMA(d[2 * gg],     a[kk], bfr[0], bfr[1]);
                MMA(d[2 * gg + 1], a[kk], bfr[2], bfr[3]);
            }
        }

        // epilogue: bf16-rounded eoff values (identical in both passes)
        #pragma unroll
        for (int gg = 0; gg < 2; ++gg)
            #pragma unroll
            for (int hi = 0; hi < 2; ++hi) {
                int f = 2 * gg + hi;
                int k0 = j * 64 + chh * 32 + gg * 16 + hi * 8 + 2 * (lane & 3);
                float cv0 = sf[W_C2 + k0]     - OFF;
                float cv1 = sf[W_C2 + k0 + 1] - OFF;
                uint32_t uA = packbf(fmaf(-2.f, d[f][0], cv0), fmaf(-2.f, d[f][1], cv1));
                uint32_t uB = packbf(fmaf(-2.f, d[f][2], cv0), fmaf(-2.f, d[f][3], cv1));
                float e00 = __uint_as_float(uA << 16);
                float e01 = __uint_as_float(uA & 0xFFFF0000u);
                float e10 = __uint_as_float(uB << 16);
                float e11 = __uint_as_float(uB & 0xFFFF0000u);
                if (jj < 16) {
                    mn[0] = fminf(mn[0], fminf(e00, e01));
                    mn[1] = fminf(mn[1], fminf(e10, e11));
                } else {
                    float T0 = sf[W_T + r0], T1 = sf[W_T + r0 + 8];
                    #pragma unroll
                    for (int cand = 0; cand < 4; ++cand) {
                        float ev  = (cand == 0) ? e00 : (cand == 1) ? e01
                                  : (cand == 2) ? e10 : e11;
                        int   row = (cand < 2) ? r0 : r0 + 8;
                        int   idx = (cand < 2) ? 0 : 1;
                        float Tv  = (cand < 2) ? T0 : T1;
                        int   k   = k0 + (cand & 1);
                        if (ev <= Tv) {
                            const float* cr = codebook + k * CH;
                            float d0 = 0.f, d1 = 0.f, d2 = 0.f, d3 = 0.f;
                            #pragma unroll
                            for (int c = 0; c < 128; c += 4) {
                                d0 = fmaf(sf[W_ZST + (c+0)*64 + row], cr[c+0], d0);
                                d1 = fmaf(sf[W_ZST + (c+1)*64 + row], cr[c+1], d1);
                                d2 = fmaf(sf[W_ZST + (c+2)*64 + row], cr[c+2], d2);
                                d3 = fmaf(sf[W_ZST + (c+3)*64 + row], cr[c+3], d3);
                            }
                            float ef = fmaf(-sf[W_RN2 + row], (d0 + d1) + (d2 + d3),
                                            sf[W_C2 + k]);
                            if (ef < be[idx]) { be[idx] = ef; bi[idx] = k; }
                        }
                    }
                }
            }
    }

    // ---- final per-vector reduce (8 slots/row, tie -> smallest index) ----
    sf[W_PE  + slot * 64 + r0]     = be[0];
    si[W_PIX + slot * 64 + r0]     = bi[0];
    sf[W_PE  + slot * 64 + r0 + 8] = be[1];
    si[W_PIX + slot * 64 + r0 + 8] = bi[1];
    __syncthreads();
    if (tid < 64) {
        float bev = sf[W_PE + tid]; int biv = si[W_PIX + tid];
        #pragma unroll
        for (int qq = 1; qq < 8; ++qq) {
            float e2 = sf[W_PE + qq * 64 + tid];
            int   i2 = si[W_PIX + qq * 64 + tid];
            if (e2 < bev || (e2 == bev && i2 < biv)) { bev = e2; biv = i2; }
        }
        si[W_SIDX + tid] = biv;
        sf[W_LS + tid] = sqrtf(fmaxf(sf[W_Z2 + tid] + bev, 0.f));
    }
    __syncthreads();
    if (tid == 0) {
        float s = 0.f;
        #pragma unroll
        for (int i = 0; i < 64; ++i) s += sf[W_LS + i];
        g_partial[blockIdx.x] = s;
    }
    __syncthreads();

    // ---- q gather (coalesced codebook reads) + coalesced store ----
    float* qr = sf + W_CB;   // [64][129] = 8256 words, fits in B-buffer region
    {
        int wrp = tid >> 5, ln = tid & 31;
        #pragma unroll
        for (int vv = 0; vv < 8; ++vv) {
            int vx = wrp * 8 + vv;
            const float* cr = codebook + si[W_SIDX + vx] * CH;
            #pragma unroll
            for (int cc = 0; cc < 4; ++cc) {
                int c = cc * 32 + ln;
                qr[vx * 129 + c] = cr[c];
            }
        }
    }
    __syncthreads();
    {
        float* obase = out + (size_t)b * (CH * 4096) + h * 64;
        const int ww = tid & 63, c0 = tid >> 6;
        #pragma unroll
        for (int it = 0; it < 32; ++it) {
            int c = it * 4 + c0;
            obase[c * 4096 + ww] = qr[ww * 129 + c];
        }
    }
}

// ---------------------------------------------------------------------------
__global__ void finalize_kernel(float* __restrict__ out) {
    __shared__ float s[256];
    int t = threadIdx.x;
    float a = 0.f;
    #pragma unroll
    for (int i = 0; i < 4; ++i) a += g_partial[t + i * 256];
    s[t] = a;
    __syncthreads();
    for (int off = 128; off > 0; off >>= 1) {
        if (t < off) s[t] += s[t + off];
        __syncthreads();
    }
    if (t == 0) {
        float mean = s[0] * (1.0f / 65536.0f);
        out[QELEMS]     = 0.25f * mean;
        out[QELEMS + 1] = mean;
    }
}

extern "C" void kernel_launch(void* const* d_in, const int* in_sizes, int n_in,
                              void* d_out, int out_size) {
    const float* x        = (const float*)d_in[0];
    const float* codebook = (const float*)d_in[1];
    float*       out      = (float*)d_out;

    prep_kernel<<<CB_K, CH>>>(codebook);

    cudaFuncSetAttribute(vq_fused, cudaFuncAttributeMaxDynamicSharedMemorySize, SMEM_BYTES);
    vq_fused<<<NBLK, 256, SMEM_BYTES>>>(x, codebook, out);

    if (out_size >= QELEMS + 2)
        finalize_kernel<<<1, 256>>>(out);
}